// round 15
// baseline (speedup 1.0000x reference)
#include <cuda_runtime.h>
#include <cuda_fp16.h>
#include <cstdint>

#define HWL    32768          // 32*32*32 spatial positions
#define CDIM   64             // in channels == out channels
#define KPROD  27             // 3*3*3 taps
#define P_TILE 128            // output positions per CTA (= GEMM M)

// Padded channels-last x in fp16: guard bands let the gather skip ALL bounds
// checks (validity folded into weights; pads are zero — harmless reads).
#define PAD_LO 560000
#define PAD_HI 700000
__device__ __align__(16) __half g_xhp[PAD_LO + HWL * CDIM + PAD_HI];
__device__ __align__(16) unsigned char g_wb[KPROD * 8192];
// per tap: 8KB fp16; rows = cout (128B each, 64 c x fp16), SW128-swizzled

__device__ __forceinline__ uint32_t s2u(const void* p) {
    uint32_t a;
    asm("{ .reg .u64 t; cvta.to.shared.u64 t, %1; cvt.u32.u64 %0, t; }"
        : "=r"(a) : "l"(p));
    return a;
}

__device__ __forceinline__ void ldmx4(uint32_t* r, uint32_t addr) {
    asm volatile("ldmatrix.sync.aligned.m8n8.x4.shared.b16 {%0,%1,%2,%3}, [%4];"
                 : "=r"(r[0]), "=r"(r[1]), "=r"(r[2]), "=r"(r[3]) : "r"(addr));
}

__device__ __forceinline__ void mma16816f16(float* d, const uint32_t* a,
                                            uint32_t b0, uint32_t b1) {
    asm volatile(
        "mma.sync.aligned.m16n8k16.row.col.f32.f16.f16.f32 "
        "{%0,%1,%2,%3}, {%4,%5,%6,%7}, {%8,%9}, {%0,%1,%2,%3};"
        : "+f"(d[0]), "+f"(d[1]), "+f"(d[2]), "+f"(d[3])
        : "r"(a[0]), "r"(a[1]), "r"(a[2]), "r"(a[3]), "r"(b0), "r"(b1));
}

// smem layout (bytes from dynamic smem base)
#define OFF_A      0
#define A_BUF_SZ   16384                     // 128 rows x 128B fp16, SW128
#define OFF_W      32768                     // weight stages: 2 x 8KB
#define OFF_META   (OFF_W + 16384)           // per-position metadata: 128 x 48B
#define SMEM_BYTES (OFF_META + 128 * 48)     // 55296 -> 3 CTAs/SM (166 KB)

// ---------------------------------------------------------------------------
// Fused prep: blocks [0,2048) transpose x -> g_xhp[PAD_LO + s*64 + c] (fp16);
//             blocks [2048,2480) weight -> fp16, pre-swizzled [k][co][c]
// ---------------------------------------------------------------------------
__global__ __launch_bounds__(256) void prep_kernel(const float* __restrict__ x,
                                                   const float* __restrict__ w) {
    const int b = blockIdx.x;
    if (b < 2048) {
        __shared__ float tile[32][33];
        const int sbase = (b & 1023) * 32;
        const int cbase = (b >> 10) * 32;
        const int tx = threadIdx.x & 31, ty = threadIdx.x >> 5;
#pragma unroll
        for (int i = 0; i < 4; ++i) {
            const int c = ty + i * 8;
            tile[c][tx] = x[(cbase + c) * HWL + sbase + tx];
        }
        __syncthreads();
#pragma unroll
        for (int i = 0; i < 4; ++i) {
            const int s = ty + i * 8;
            g_xhp[PAD_LO + (sbase + s) * CDIM + cbase + tx] =
                __float2half_rn(tile[tx][s]);
        }
    } else {
        const int tid = (b - 2048) * 256 + threadIdx.x;   // < 27*4096 exactly
        const int k   = tid >> 12;
        const int rem = tid & 4095;
        const int co  = rem >> 6;
        const int c   = rem & 63;
        const float v = w[(co * CDIM + c) * KPROD + k];
        const uint32_t off = co * 128 + c * 2;            // row=co, 128B/row
        const uint32_t sw  = off ^ ((off >> 3) & 0x70);   // SW128
        *(__half*)(g_wb + k * 8192 + sw) = __float2half_rn(v);
    }
}

// stage one tap's 8KB fp16 weight slab via cp.async (identity copy)
__device__ __forceinline__ void stage_w(uint32_t dst, int k, int t) {
    const char* src = (const char*)g_wb + k * 8192 + t * 16;
    const uint32_t d = dst + t * 16;
#pragma unroll
    for (int i = 0; i < 2; ++i)
        asm volatile("cp.async.cg.shared.global [%0], [%1], 16;"
                     :: "r"(d + i * 4096), "l"(src + i * 4096) : "memory");
    asm volatile("cp.async.commit_group;");
}

// convert one corner (4 fp16 channels) and accumulate with weight kw
#define CVTACC(u, kw)                                                        \
    do { const float2 _a = __half22float2(*(const __half2*)&(u).x);          \
         const float2 _b = __half22float2(*(const __half2*)&(u).y);          \
         const float _k = (kw);                                              \
         v0 += _k * _a.x; v1 += _k * _a.y;                                   \
         v2 += _k * _b.x; v3 += _k * _b.y; } while (0)

// ---------------------------------------------------------------------------
// Gather one tap into an A buffer (fp16, SW128 rows = position).
//   Phase M (once per tap per warp): per-position metadata — 8 corner
//     weights (mask folded) + base byte-offset — to warp-private smem.
//   Phase G (8 passes x 2 positions): broadcast-LDS metadata, 8 constant-
//     offset fp16 corner loads (128B contiguous each), interp in fp32,
//     round to fp16, single swizzled STS.64.
// ---------------------------------------------------------------------------
__device__ __forceinline__ void gather_tap(
    char* smem, uint32_t abase, int k,
    const float* __restrict__ offset, const float* __restrict__ mask,
    int pw, int sub, int lane16, int pbase)
{
    const int ki = k / 9;
    const int kj = (k % 9) / 3;
    const int kk = k % 3;

    // ---- Phase M: metadata for this warp's 16 positions ----
    {
        const int mp  = pw + lane16;          // position in tile
        const int pgm = pbase + mp;           // global position
        const int pl  = pgm & 31;
        const int pwo = (pgm >> 5) & 31;
        const int pho = pgm >> 10;

        const float och = offset[(k * 3 + 0) * HWL + pgm];
        const float ocw = offset[(k * 3 + 1) * HWL + pgm];
        const float ocl = offset[(k * 3 + 2) * HWL + pgm];
        const float m   = mask[k * HWL + pgm];

        const float ch = och + (float)(pho - 1 + ki);
        const float cw = ocw + (float)(pwo - 1 + kj);
        const float cl = ocl + (float)(pl - 1 + kk);

        const float hf = floorf(ch), wf = floorf(cw), lf = floorf(cl);
        int h0 = (int)hf, w0 = (int)wf, l0 = (int)lf;
        const float fh = ch - hf, fw = cw - wf, fl = cl - lf;

        const float wh0 = ((unsigned)h0 < 32u)       ? 1.f - fh : 0.f;
        const float wh1 = ((unsigned)(h0 + 1) < 32u) ? fh       : 0.f;
        const float ww0 = ((unsigned)w0 < 32u)       ? 1.f - fw : 0.f;
        const float ww1 = ((unsigned)(w0 + 1) < 32u) ? fw       : 0.f;
        const float wl0 = ((unsigned)l0 < 32u)       ? 1.f - fl : 0.f;
        const float wl1 = ((unsigned)(l0 + 1) < 32u) ? fl       : 0.f;

        h0 = max(-8, min(h0, 40));
        w0 = max(-8, min(w0, 40));
        l0 = max(-8, min(l0, 40));
        // pre-scaled BYTE offset of corner base (fp16 elements, CDIM stride)
        const int base = (PAD_LO + ((h0 * 32 + w0) * 32 + l0) * CDIM) * 2;

        const float w00 = wh0 * ww0 * m, w01 = wh0 * ww1 * m;
        const float w10 = wh1 * ww0 * m, w11 = wh1 * ww1 * m;

        if (lane16 == (threadIdx.x & 31)) {   // lanes 0..15 only
            char* mrow = smem + OFF_META + mp * 48;
            *(float4*)(mrow)      = make_float4(w00 * wl0, w00 * wl1,
                                                w01 * wl0, w01 * wl1);
            *(float4*)(mrow + 16) = make_float4(w10 * wl0, w10 * wl1,
                                                w11 * wl0, w11 * wl1);
            *(int*)(mrow + 32)    = base;
        }
    }
    __syncwarp();

    // ---- Phase G: gather using metadata ----
#pragma unroll 2
    for (int iter = 0; iter < 8; ++iter) {
        const int idx = iter * 2 + sub;
        const int p   = pw + idx;

        const char* mrow = smem + OFF_META + p * 48;
        const float4 ka = *(const float4*)(mrow);
        const float4 kb = *(const float4*)(mrow + 16);
        const int  base = *(const int*)(mrow + 32);

        const char* bp = (const char*)g_xhp + base + lane16 * 8;

        // 8 corner loads (fp16): constant byte offsets, back-to-back, 128B each
        const uint2 u000 = *(const uint2*)(bp + 0);
        const uint2 u001 = *(const uint2*)(bp + 128);
        const uint2 u010 = *(const uint2*)(bp + 4096);
        const uint2 u011 = *(const uint2*)(bp + 4224);
        const uint2 u100 = *(const uint2*)(bp + 131072);
        const uint2 u101 = *(const uint2*)(bp + 131200);
        const uint2 u110 = *(const uint2*)(bp + 135168);
        const uint2 u111 = *(const uint2*)(bp + 135296);

        float v0 = 0.f, v1 = 0.f, v2 = 0.f, v3 = 0.f;
        CVTACC(u000, ka.x);
        CVTACC(u001, ka.y);
        CVTACC(u010, ka.z);
        CVTACC(u011, ka.w);
        CVTACC(u100, kb.x);
        CVTACC(u101, kb.y);
        CVTACC(u110, kb.z);
        CVTACC(u111, kb.w);

        // round to fp16 (mask already folded into weights)
        const __half2 p01 = __floats2half2_rn(v0, v1);
        const __half2 p23 = __floats2half2_rn(v2, v3);
        uint2 sv;
        sv.x = *(const uint32_t*)&p01;
        sv.y = *(const uint32_t*)&p23;

        // SW128-swizzled STS.64: row = p (128B), cols = 4 channels (8B)
        const uint32_t off = (uint32_t)(p * 128 + lane16 * 8);
        const uint32_t sw  = off ^ (uint32_t)((p & 7) << 4);
        *(uint2*)(smem + abase + sw) = sv;
    }
}

// ---------------------------------------------------------------------------
// Fused deformable conv3d, software-pipelined, fp16 single-term GEMM.
//   3 CTAs/SM (84-reg target): +50% warps for latency hiding.
//   iteration k: gather(tap k+1 -> A buf (k+1)&1) | GEMM(tap k from buf k&1)
// ---------------------------------------------------------------------------
__global__ __launch_bounds__(256, 3)
void deform_conv3d_kernel(const float* __restrict__ offset,
                          const float* __restrict__ mask,
                          float* __restrict__ out) {
    extern __shared__ char smem[];
    const uint32_t sb = s2u(smem);

    const int t      = threadIdx.x;
    const int lane   = t & 31;
    const int warp   = t >> 5;
    const int lane16 = lane & 15;
    const int sub    = lane >> 4;
    const int pbase  = blockIdx.x * P_TILE;
    const int pw     = warp * 16;

    // GEMM warp tile: 4(p) x 2(co) warp grid, 32p x 32co per warp
    const int pblk = (warp & 3) * 32;
    const int cblk = (warp >> 2) * 32;

    const int lrr = lane & 7;
    const int a_row0 = pblk + lrr + ((lane >> 3) & 1) * 8;   // p-tile 0 row
    const int b_row0 = cblk + lrr + ((lane >> 4) & 1) * 8;   // co-pair 0 row
    const int a_colh = (lane >> 4) & 1;
    const int b_colh = (lane >> 3) & 1;

    float acc[2][4][4];
#pragma unroll
    for (int i = 0; i < 2; ++i)
#pragma unroll
        for (int j = 0; j < 4; ++j)
#pragma unroll
            for (int q = 0; q < 4; ++q) acc[i][j][q] = 0.f;

    // prologue: weights tap 0 + gather tap 0 into buffer 0
    stage_w(sb + OFF_W, 0, t);
    gather_tap(smem, OFF_A, 0, offset, mask, pw, sub, lane16, pbase);
    __syncthreads();

    for (int k = 0; k < KPROD; ++k) {
        if (k < KPROD - 1) {
            stage_w(sb + OFF_W + (uint32_t)((k + 1) & 1) * 8192, k + 1, t);
            gather_tap(smem, OFF_A + (uint32_t)((k + 1) & 1) * A_BUF_SZ, k + 1,
                       offset, mask, pw, sub, lane16, pbase);
        }

        if (k == KPROD - 1)
            asm volatile("cp.async.wait_group 0;" ::: "memory");
        else
            asm volatile("cp.async.wait_group 1;" ::: "memory");

        // ---- GEMM: tap k (fp16 single-term) ----
        const uint32_t wS  = sb + OFF_W + (uint32_t)(k & 1) * 8192;
        const uint32_t a0b = sb + OFF_A + (uint32_t)(k & 1) * A_BUF_SZ;
#pragma unroll
        for (int ks = 0; ks < 4; ++ks) {
            const uint32_t cbA = ((uint32_t)(ks * 32 + a_colh * 16));
            const uint32_t cbB = ((uint32_t)(ks * 32 + b_colh * 16));
            uint32_t A0[2][4], B0[2][4];
#pragma unroll
            for (int pt = 0; pt < 2; ++pt) {
                const int r = a_row0 + pt * 16;
                ldmx4(A0[pt], a0b + (uint32_t)(r * 128)
                                  + (cbA ^ (uint32_t)((r & 7) << 4)));
            }
#pragma unroll
            for (int b2 = 0; b2 < 2; ++b2) {
                const int r = b_row0 + b2 * 16;
                ldmx4(B0[b2], wS + (uint32_t)(r * 128)
                                 + (cbB ^ (uint32_t)((r & 7) << 4)));
            }
#pragma unroll
            for (int pt = 0; pt < 2; ++pt)
#pragma unroll
                for (int bt = 0; bt < 4; ++bt) {
                    const int b2 = bt >> 1, hh = (bt & 1) * 2;
                    mma16816f16(acc[pt][bt], A0[pt], B0[b2][hh], B0[b2][hh + 1]);
                }
        }
        __syncthreads();
    }

    // ---- epilogue: D frag layout -> out[co][p] ----
    const int prow = lane >> 2;
    const int pcol = (lane & 3) * 2;
#pragma unroll
    for (int pt = 0; pt < 2; ++pt)
#pragma unroll
        for (int bt = 0; bt < 4; ++bt) {
            const int p0 = pbase + pblk + pt * 16 + prow;
            const int co = cblk + bt * 8 + pcol;
            out[(size_t)co * HWL + p0]           = acc[pt][bt][0];
            out[(size_t)(co + 1) * HWL + p0]     = acc[pt][bt][1];
            out[(size_t)co * HWL + p0 + 8]       = acc[pt][bt][2];
            out[(size_t)(co + 1) * HWL + p0 + 8] = acc[pt][bt][3];
        }
}

// ---------------------------------------------------------------------------
extern "C" void kernel_launch(void* const* d_in, const int* in_sizes, int n_in,
                              void* d_out, int out_size) {
    const float* x = nullptr;
    const float* offset = nullptr;
    const float* mask = nullptr;
    const float* weight = nullptr;
    for (int i = 0; i < n_in; ++i) {
        switch (in_sizes[i]) {
            case 2097152: x      = (const float*)d_in[i]; break;  // [1,64,32,32,32]
            case 2654208: offset = (const float*)d_in[i]; break;  // [1,81,32,32,32]
            case 884736:  mask   = (const float*)d_in[i]; break;  // [1,27,32,32,32]
            case 110592:  weight = (const float*)d_in[i]; break;  // [64,64,3,3,3]
        }
    }

    static bool s_attr_done = false;
    if (!s_attr_done) {
        cudaFuncSetAttribute(deform_conv3d_kernel,
                             cudaFuncAttributeMaxDynamicSharedMemorySize, SMEM_BYTES);
        s_attr_done = true;
    }

    prep_kernel<<<2480, 256>>>(x, weight);
    deform_conv3d_kernel<<<HWL / P_TILE, 256, SMEM_BYTES>>>(offset, mask, (float*)d_out);
}